// round 1
// baseline (speedup 1.0000x reference)
#include <cuda_runtime.h>
#include <math.h>
#include <stdint.h>

// Problem constants (fixed by the dataset)
#define N_NODES 100000
#define E_EDGES 1600000
#define K_IN    192
#define F_LAT   64
#define F_OUT   128

// ---------------------------------------------------------------------------
// Scratch (device globals; allocation inside kernel_launch is forbidden).
// Declared as float4 arrays to guarantee 16B alignment for vector ld/st and
// for cp.reduce.async.bulk.
// ---------------------------------------------------------------------------
__device__ float4 g_x4[N_NODES * (F_LAT / 4)];      // x = relu(embed@W1+b)   [N,64]
__device__ float4 g_feat4[N_NODES * (F_OUT / 4)];   // feat = x@W2            [N,128]
__device__ float4 g_accum4[N_NODES * (F_OUT / 4)];  // unnormalized aggregation
__device__ float  g_el[N_NODES];
__device__ float  g_er[N_NODES];
__device__ float  g_denom[N_NODES];

// ---------------------------------------------------------------------------
// Init: zero accumulators (replayed every graph launch)
// ---------------------------------------------------------------------------
__global__ void __launch_bounds__(256) init_kernel() {
    int i = blockIdx.x * blockDim.x + threadIdx.x;
    int stride = gridDim.x * blockDim.x;
    const int n4 = N_NODES * (F_OUT / 4);
    float4 z = make_float4(0.f, 0.f, 0.f, 0.f);
    for (int idx = i; idx < n4; idx += stride) g_accum4[idx] = z;
    for (int idx = i; idx < N_NODES; idx += stride) g_denom[idx] = 0.f;
}

// ---------------------------------------------------------------------------
// K1: x = relu(embed @ W_lin + b_lin)   [N,192] x [192,64] -> [N,64]
// Block tile: 64 nodes x 64 outputs, 256 threads, 4x4 per thread.
// K split into 3 chunks of 64 so smem stays under 48KB.
// ---------------------------------------------------------------------------
__global__ void __launch_bounds__(256) k1_linear(const float* __restrict__ embed,
                                                 const float* __restrict__ Wl,
                                                 const float* __restrict__ bl) {
    __shared__ float sE[64][68];   // padded rows: 272B stride (16B-aligned)
    __shared__ float sW[64][64];

    int t = threadIdx.x;
    int base = blockIdx.x * 64;
    int tm = t >> 4;       // 0..15
    int tn = t & 15;       // 0..15

    float acc[4][4];
#pragma unroll
    for (int r = 0; r < 4; r++)
#pragma unroll
        for (int c = 0; c < 4; c++) acc[r][c] = 0.f;

    for (int kc = 0; kc < 3; kc++) {
#pragma unroll
        for (int l = 0; l < 4; l++) {
            int idx = l * 256 + t;          // float4 index, 0..1023
            int r = idx >> 4;               // 0..63
            int c = (idx & 15) * 4;         // 0..60
            int node = base + r;
            float4 v = make_float4(0.f, 0.f, 0.f, 0.f);
            if (node < N_NODES)
                v = *reinterpret_cast<const float4*>(&embed[(size_t)node * K_IN + kc * 64 + c]);
            *reinterpret_cast<float4*>(&sE[r][c]) = v;
            // W chunk is a contiguous 64x64 block (full row width)
            float4 w = *reinterpret_cast<const float4*>(&Wl[(size_t)kc * 4096 + idx * 4]);
            *reinterpret_cast<float4*>(&sW[0][0] + idx * 4) = w;
        }
        __syncthreads();

#pragma unroll 16
        for (int k = 0; k < 64; k++) {
            float a0 = sE[tm * 4 + 0][k];
            float a1 = sE[tm * 4 + 1][k];
            float a2 = sE[tm * 4 + 2][k];
            float a3 = sE[tm * 4 + 3][k];
            float4 bb = *reinterpret_cast<const float4*>(&sW[k][tn * 4]);
            acc[0][0] += a0 * bb.x; acc[0][1] += a0 * bb.y; acc[0][2] += a0 * bb.z; acc[0][3] += a0 * bb.w;
            acc[1][0] += a1 * bb.x; acc[1][1] += a1 * bb.y; acc[1][2] += a1 * bb.z; acc[1][3] += a1 * bb.w;
            acc[2][0] += a2 * bb.x; acc[2][1] += a2 * bb.y; acc[2][2] += a2 * bb.z; acc[2][3] += a2 * bb.w;
            acc[3][0] += a3 * bb.x; acc[3][1] += a3 * bb.y; acc[3][2] += a3 * bb.z; acc[3][3] += a3 * bb.w;
        }
        __syncthreads();
    }

    float4 bias = *reinterpret_cast<const float4*>(&bl[tn * 4]);
#pragma unroll
    for (int r = 0; r < 4; r++) {
        int node = base + tm * 4 + r;
        if (node < N_NODES) {
            float4 o;
            o.x = fmaxf(acc[r][0] + bias.x, 0.f);
            o.y = fmaxf(acc[r][1] + bias.y, 0.f);
            o.z = fmaxf(acc[r][2] + bias.z, 0.f);
            o.w = fmaxf(acc[r][3] + bias.w, 0.f);
            g_x4[(size_t)node * (F_LAT / 4) + tn] = o;
        }
    }
}

// ---------------------------------------------------------------------------
// K2: feat = x @ W_gat, el = feat@attn_l, er = feat@attn_r
// Block tile: 64 nodes; N=128 handled in two 64-wide halves.
// ---------------------------------------------------------------------------
__global__ void __launch_bounds__(256) k2_gatproj(const float* __restrict__ Wg,
                                                  const float* __restrict__ attn_l,
                                                  const float* __restrict__ attn_r) {
    __shared__ float sX[64][68];
    __shared__ float sW[64][64];
    __shared__ float sEl[64];
    __shared__ float sEr[64];

    int t = threadIdx.x;
    int base = blockIdx.x * 64;
    int tm = t >> 4;
    int tn = t & 15;

    if (t < 64) { sEl[t] = 0.f; sEr[t] = 0.f; }

    // load x tile [64,64]
#pragma unroll
    for (int l = 0; l < 4; l++) {
        int idx = l * 256 + t;
        int r = idx >> 4;
        int c = (idx & 15) * 4;
        int node = base + r;
        float4 v = make_float4(0.f, 0.f, 0.f, 0.f);
        if (node < N_NODES)
            v = g_x4[(size_t)node * (F_LAT / 4) + (c >> 2)];
        *reinterpret_cast<float4*>(&sX[r][c]) = v;
    }

    for (int nh = 0; nh < 2; nh++) {
        // load W_gat chunk: rows 0..63, cols nh*64..nh*64+63 (row stride 128)
#pragma unroll
        for (int l = 0; l < 4; l++) {
            int idx = l * 256 + t;
            int r = idx >> 4;
            int c = (idx & 15) * 4;
            float4 w = *reinterpret_cast<const float4*>(&Wg[(size_t)r * F_OUT + nh * 64 + c]);
            *reinterpret_cast<float4*>(&sW[0][0] + r * 64 + c) = w;
        }
        __syncthreads();

        float acc[4][4];
#pragma unroll
        for (int r = 0; r < 4; r++)
#pragma unroll
            for (int c = 0; c < 4; c++) acc[r][c] = 0.f;

#pragma unroll 16
        for (int k = 0; k < 64; k++) {
            float a0 = sX[tm * 4 + 0][k];
            float a1 = sX[tm * 4 + 1][k];
            float a2 = sX[tm * 4 + 2][k];
            float a3 = sX[tm * 4 + 3][k];
            float4 bb = *reinterpret_cast<const float4*>(&sW[k][tn * 4]);
            acc[0][0] += a0 * bb.x; acc[0][1] += a0 * bb.y; acc[0][2] += a0 * bb.z; acc[0][3] += a0 * bb.w;
            acc[1][0] += a1 * bb.x; acc[1][1] += a1 * bb.y; acc[1][2] += a1 * bb.z; acc[1][3] += a1 * bb.w;
            acc[2][0] += a2 * bb.x; acc[2][1] += a2 * bb.y; acc[2][2] += a2 * bb.z; acc[2][3] += a2 * bb.w;
            acc[3][0] += a3 * bb.x; acc[3][1] += a3 * bb.y; acc[3][2] += a3 * bb.z; acc[3][3] += a3 * bb.w;
        }

        float4 al = *reinterpret_cast<const float4*>(&attn_l[nh * 64 + tn * 4]);
        float4 ar = *reinterpret_cast<const float4*>(&attn_r[nh * 64 + tn * 4]);
#pragma unroll
        for (int r = 0; r < 4; r++) {
            int node = base + tm * 4 + r;
            if (node < N_NODES) {
                float4 o = make_float4(acc[r][0], acc[r][1], acc[r][2], acc[r][3]);
                g_feat4[(size_t)node * (F_OUT / 4) + (nh * 64 + tn * 4) / 4] = o;
                float pl = o.x * al.x + o.y * al.y + o.z * al.z + o.w * al.w;
                float pr = o.x * ar.x + o.y * ar.y + o.z * ar.z + o.w * ar.w;
                atomicAdd(&sEl[tm * 4 + r], pl);
                atomicAdd(&sEr[tm * 4 + r], pr);
            }
        }
        __syncthreads();
    }

    if (t < 64) {
        int node = base + t;
        if (node < N_NODES) {
            g_el[node] = sEl[t];
            g_er[node] = sEr[t];
        }
    }
}

// ---------------------------------------------------------------------------
// Edge pass: warp per edge.
//   e   = leaky_relu(el[src]+er[dst])
//   ee  = exp(e)                      (no max-shift needed: |e| is O(1))
//   denom[dst] += ee                  (scalar atomic, 1 per edge)
//   accum[dst] += ee * feat[src]      (512B TMA bulk f32-add reduction — avoids
//                                      205M per-lane atomics, rides LTS path)
// ---------------------------------------------------------------------------
__global__ void __launch_bounds__(256) edge_kernel(const int* __restrict__ src,
                                                   const int* __restrict__ dst,
                                                   int num_edges) {
    __shared__ __align__(16) float sbuf[8][F_OUT];   // one 512B row per warp

    int gw = (blockIdx.x * 256 + threadIdx.x) >> 5;  // global warp = edge id
    int lane = threadIdx.x & 31;
    int wl = threadIdx.x >> 5;
    if (gw >= num_edges) return;                     // warp-uniform

    int s = src[gw];
    int d = dst[gw];
    float e = g_el[s] + g_er[d];
    e = (e > 0.f) ? e : 0.2f * e;
    float ee = __expf(e);

    if (lane == 0) atomicAdd(&g_denom[d], ee);

    float4 f = g_feat4[(size_t)s * (F_OUT / 4) + lane];
    float4 v = make_float4(f.x * ee, f.y * ee, f.z * ee, f.w * ee);
    reinterpret_cast<float4*>(sbuf[wl])[lane] = v;
    __syncwarp();

    if (lane == 0) {
        asm volatile("fence.proxy.async.shared::cta;" ::: "memory");
        unsigned saddr = (unsigned)__cvta_generic_to_shared(sbuf[wl]);
        float* gp = reinterpret_cast<float*>(&g_accum4[(size_t)d * (F_OUT / 4)]);
        asm volatile(
            "cp.reduce.async.bulk.global.shared::cta.bulk_group.add.f32 [%0], [%1], %2;"
            :: "l"(gp), "r"(saddr), "r"(512u) : "memory");
        asm volatile("cp.async.bulk.commit_group;" ::: "memory");
        asm volatile("cp.async.bulk.wait_group 0;" ::: "memory");
    }
}

// ---------------------------------------------------------------------------
// Finalize: y = accum/denom + b_gat; out = [mu | tanh(logvar)]
// Thread per float4 of y.
// ---------------------------------------------------------------------------
__global__ void __launch_bounds__(256) final_kernel(const float* __restrict__ b_gat,
                                                    float* __restrict__ out) {
    int idx = blockIdx.x * 256 + threadIdx.x;        // float4 index
    const int total = N_NODES * (F_OUT / 4);
    if (idx >= total) return;
    int node = idx >> 5;
    int q = idx & 31;
    int col = q * 4;

    float4 a = g_accum4[idx];
    float den = g_denom[node];
    float inv = (den > 0.f) ? (1.0f / den) : 0.f;    // empty segment: accum==0 anyway
    float4 bg = *reinterpret_cast<const float4*>(&b_gat[col]);
    float4 y = make_float4(a.x * inv + bg.x, a.y * inv + bg.y,
                           a.z * inv + bg.z, a.w * inv + bg.w);

    if (col < 64) {
        *reinterpret_cast<float4*>(&out[(size_t)node * 64 + col]) = y;
    } else {
        float4 z = make_float4(tanhf(y.x), tanhf(y.y), tanhf(y.z), tanhf(y.w));
        *reinterpret_cast<float4*>(&out[(size_t)N_NODES * 64 + (size_t)node * 64 + (col - 64)]) = z;
    }
}

// ---------------------------------------------------------------------------
// Launch
// ---------------------------------------------------------------------------
extern "C" void kernel_launch(void* const* d_in, const int* in_sizes, int n_in,
                              void* d_out, int out_size) {
    const float* embed  = (const float*)d_in[0];
    const int*   src    = (const int*)d_in[1];
    const int*   dst    = (const int*)d_in[2];
    const float* W_lin  = (const float*)d_in[3];
    const float* b_lin  = (const float*)d_in[4];
    const float* W_gat  = (const float*)d_in[5];
    const float* attn_l = (const float*)d_in[6];
    const float* attn_r = (const float*)d_in[7];
    const float* b_gat  = (const float*)d_in[8];
    float* out = (float*)d_out;

    int num_edges = in_sizes[1];   // E

    init_kernel<<<4096, 256>>>();
    k1_linear<<<(N_NODES + 63) / 64, 256>>>(embed, W_lin, b_lin);
    k2_gatproj<<<(N_NODES + 63) / 64, 256>>>(W_gat, attn_l, attn_r);
    edge_kernel<<<(num_edges + 7) / 8, 256>>>(src, dst, num_edges);
    final_kernel<<<(N_NODES * (F_OUT / 4) + 255) / 256, 256>>>(b_gat, out);
}

// round 2
// speedup vs baseline: 1.2886x; 1.2886x over previous
#include <cuda_runtime.h>
#include <math.h>
#include <stdint.h>

#define N_NODES 100000
#define K_IN    192
#define F_LAT   64
#define F_OUT   128
#define EPB     8      // edges per warp in the edge pass

// ---------------------------------------------------------------------------
// Scratch (device globals; allocation inside kernel_launch is forbidden).
// ---------------------------------------------------------------------------
__device__ float4 g_feat4[N_NODES * (F_OUT / 4)];   // feat = x@W2            [N,128]
__device__ float4 g_accum4[N_NODES * (F_OUT / 4)];  // unnormalized aggregation
__device__ float  g_el[N_NODES];
__device__ float  g_er[N_NODES];
__device__ float  g_denom[N_NODES];

// ---------------------------------------------------------------------------
// Init: zero accumulators (replayed every graph launch)
// ---------------------------------------------------------------------------
__global__ void __launch_bounds__(256) init_kernel() {
    int i = blockIdx.x * blockDim.x + threadIdx.x;
    int stride = gridDim.x * blockDim.x;
    const int n4 = N_NODES * (F_OUT / 4);
    float4 z = make_float4(0.f, 0.f, 0.f, 0.f);
    for (int idx = i; idx < n4; idx += stride) g_accum4[idx] = z;
    for (int idx = i; idx < N_NODES; idx += stride) g_denom[idx] = 0.f;
}

// ---------------------------------------------------------------------------
// Fused node kernel:
//   phase A: x = relu(embed @ W_lin + b_lin)     [64-node tile, held in smem]
//   phase B: feat = x @ W_gat ; el = feat@attn_l ; er = feat@attn_r
// Block: 64 nodes, 256 threads, 4x4 register microtile.
// The embed smem tile is REUSED as the x tile (no global round trip).
// ---------------------------------------------------------------------------
__global__ void __launch_bounds__(256) node_kernel(const float* __restrict__ embed,
                                                   const float* __restrict__ Wl,
                                                   const float* __restrict__ bl,
                                                   const float* __restrict__ Wg,
                                                   const float* __restrict__ attn_l,
                                                   const float* __restrict__ attn_r) {
    __shared__ float sA[64][68];   // embed chunk, then reused as x tile
    __shared__ float sW[64][64];
    __shared__ float sEl[64];
    __shared__ float sEr[64];

    int t = threadIdx.x;
    int base = blockIdx.x * 64;
    int tm = t >> 4;       // 0..15
    int tn = t & 15;       // 0..15

    if (t < 64) { sEl[t] = 0.f; sEr[t] = 0.f; }

    float acc[4][4];
#pragma unroll
    for (int r = 0; r < 4; r++)
#pragma unroll
        for (int c = 0; c < 4; c++) acc[r][c] = 0.f;

    // ---- phase A: x = relu(embed @ W_lin + b) ----
    for (int kc = 0; kc < 3; kc++) {
#pragma unroll
        for (int l = 0; l < 4; l++) {
            int idx = l * 256 + t;          // float4 index, 0..1023
            int r = idx >> 4;               // 0..63
            int c = (idx & 15) * 4;         // 0..60
            int node = base + r;
            float4 v = make_float4(0.f, 0.f, 0.f, 0.f);
            if (node < N_NODES)
                v = *reinterpret_cast<const float4*>(&embed[(size_t)node * K_IN + kc * 64 + c]);
            *reinterpret_cast<float4*>(&sA[r][c]) = v;
            float4 w = *reinterpret_cast<const float4*>(&Wl[(size_t)kc * 4096 + idx * 4]);
            *reinterpret_cast<float4*>(&sW[0][0] + idx * 4) = w;
        }
        __syncthreads();

#pragma unroll 16
        for (int k = 0; k < 64; k++) {
            float a0 = sA[tm * 4 + 0][k];
            float a1 = sA[tm * 4 + 1][k];
            float a2 = sA[tm * 4 + 2][k];
            float a3 = sA[tm * 4 + 3][k];
            float4 bb = *reinterpret_cast<const float4*>(&sW[k][tn * 4]);
            acc[0][0] += a0 * bb.x; acc[0][1] += a0 * bb.y; acc[0][2] += a0 * bb.z; acc[0][3] += a0 * bb.w;
            acc[1][0] += a1 * bb.x; acc[1][1] += a1 * bb.y; acc[1][2] += a1 * bb.z; acc[1][3] += a1 * bb.w;
            acc[2][0] += a2 * bb.x; acc[2][1] += a2 * bb.y; acc[2][2] += a2 * bb.z; acc[2][3] += a2 * bb.w;
            acc[3][0] += a3 * bb.x; acc[3][1] += a3 * bb.y; acc[3][2] += a3 * bb.z; acc[3][3] += a3 * bb.w;
        }
        __syncthreads();   // all reads of sA done -> safe to overwrite below
    }

    // write x = relu(acc + bias) back into sA (reused as the x tile)
    {
        float4 bias = *reinterpret_cast<const float4*>(&bl[tn * 4]);
#pragma unroll
        for (int r = 0; r < 4; r++) {
            sA[tm * 4 + r][tn * 4 + 0] = fmaxf(acc[r][0] + bias.x, 0.f);
            sA[tm * 4 + r][tn * 4 + 1] = fmaxf(acc[r][1] + bias.y, 0.f);
            sA[tm * 4 + r][tn * 4 + 2] = fmaxf(acc[r][2] + bias.z, 0.f);
            sA[tm * 4 + r][tn * 4 + 3] = fmaxf(acc[r][3] + bias.w, 0.f);
        }
    }
    __syncthreads();

    // ---- phase B: feat = x @ W_gat (two 64-wide halves), el/er dots ----
    for (int nh = 0; nh < 2; nh++) {
#pragma unroll
        for (int l = 0; l < 4; l++) {
            int idx = l * 256 + t;
            int r = idx >> 4;
            int c = (idx & 15) * 4;
            float4 w = *reinterpret_cast<const float4*>(&Wg[(size_t)r * F_OUT + nh * 64 + c]);
            *reinterpret_cast<float4*>(&sW[0][0] + r * 64 + c) = w;
        }
        __syncthreads();

#pragma unroll
        for (int r = 0; r < 4; r++)
#pragma unroll
            for (int c = 0; c < 4; c++) acc[r][c] = 0.f;

#pragma unroll 16
        for (int k = 0; k < 64; k++) {
            float a0 = sA[tm * 4 + 0][k];
            float a1 = sA[tm * 4 + 1][k];
            float a2 = sA[tm * 4 + 2][k];
            float a3 = sA[tm * 4 + 3][k];
            float4 bb = *reinterpret_cast<const float4*>(&sW[k][tn * 4]);
            acc[0][0] += a0 * bb.x; acc[0][1] += a0 * bb.y; acc[0][2] += a0 * bb.z; acc[0][3] += a0 * bb.w;
            acc[1][0] += a1 * bb.x; acc[1][1] += a1 * bb.y; acc[1][2] += a1 * bb.z; acc[1][3] += a1 * bb.w;
            acc[2][0] += a2 * bb.x; acc[2][1] += a2 * bb.y; acc[2][2] += a2 * bb.z; acc[2][3] += a2 * bb.w;
            acc[3][0] += a3 * bb.x; acc[3][1] += a3 * bb.y; acc[3][2] += a3 * bb.z; acc[3][3] += a3 * bb.w;
        }

        float4 al = *reinterpret_cast<const float4*>(&attn_l[nh * 64 + tn * 4]);
        float4 ar = *reinterpret_cast<const float4*>(&attn_r[nh * 64 + tn * 4]);
#pragma unroll
        for (int r = 0; r < 4; r++) {
            int node = base + tm * 4 + r;
            if (node < N_NODES) {
                float4 o = make_float4(acc[r][0], acc[r][1], acc[r][2], acc[r][3]);
                g_feat4[(size_t)node * (F_OUT / 4) + (nh * 16 + tn)] = o;
                float pl = o.x * al.x + o.y * al.y + o.z * al.z + o.w * al.w;
                float pr = o.x * ar.x + o.y * ar.y + o.z * ar.z + o.w * ar.w;
                atomicAdd(&sEl[tm * 4 + r], pl);
                atomicAdd(&sEr[tm * 4 + r], pr);
            }
        }
        __syncthreads();
    }

    if (t < 64) {
        int node = base + t;
        if (node < N_NODES) {
            g_el[node] = sEl[t];
            g_er[node] = sEr[t];
        }
    }
}

// ---------------------------------------------------------------------------
// Edge pass v2: EPB edges per warp, batched TMA bulk f32-add reductions.
//   - lanes 0..ne-1 prefetch src/dst + compute ee = exp(leaky(el+er))
//   - all 8 feat gathers issued back-to-back (MLP=8)
//   - 8 cp.reduce.async.bulk issued, ONE commit+wait per warp (was: per edge)
// ---------------------------------------------------------------------------
__global__ void __launch_bounds__(256, 4) edge_kernel(const int* __restrict__ src,
                                                      const int* __restrict__ dst,
                                                      int num_edges) {
    __shared__ __align__(16) float sbuf[8][EPB][F_OUT];   // 32 KB
    __shared__ float sEE[8][EPB];
    __shared__ int   sD[8][EPB];

    int lane = threadIdx.x & 31;
    int wl = threadIdx.x >> 5;
    long long ebase = ((long long)blockIdx.x * 8 + wl) * EPB;
    if (ebase >= num_edges) return;                 // warp-uniform
    int ne = (int)min((long long)EPB, (long long)num_edges - ebase);

    int myS = 0;
    if (lane < ne) {
        myS = src[ebase + lane];
        int myD = dst[ebase + lane];
        float e = g_el[myS] + g_er[myD];
        e = (e > 0.f) ? e : 0.2f * e;
        sEE[wl][lane] = __expf(e);
        sD[wl][lane] = myD;
    }
    __syncwarp();

    // gather all EPB feat rows (independent loads -> high MLP)
    float4 f[EPB];
#pragma unroll
    for (int j = 0; j < EPB; j++) {
        int s = __shfl_sync(0xffffffffu, myS, j);   // lane>=ne contributed node 0 (safe)
        f[j] = g_feat4[(size_t)s * (F_OUT / 4) + lane];
    }

    // scale + stage to smem
#pragma unroll
    for (int j = 0; j < EPB; j++) {
        float ee = sEE[wl][j];                      // garbage for j>=ne: never reduced
        float4 v = make_float4(f[j].x * ee, f[j].y * ee, f[j].z * ee, f[j].w * ee);
        reinterpret_cast<float4*>(sbuf[wl][j])[lane] = v;
    }
    __syncwarp();

    if (lane == 0) {
        asm volatile("fence.proxy.async.shared::cta;" ::: "memory");
        for (int j = 0; j < ne; j++) {
            int d = sD[wl][j];
            atomicAdd(&g_denom[d], sEE[wl][j]);
            unsigned saddr = (unsigned)__cvta_generic_to_shared(sbuf[wl][j]);
            float* gp = reinterpret_cast<float*>(&g_accum4[(size_t)d * (F_OUT / 4)]);
            asm volatile(
                "cp.reduce.async.bulk.global.shared::cta.bulk_group.add.f32 [%0], [%1], %2;"
                :: "l"(gp), "r"(saddr), "r"((unsigned)(F_OUT * 4)) : "memory");
        }
        asm volatile("cp.async.bulk.commit_group;" ::: "memory");
        asm volatile("cp.async.bulk.wait_group 0;" ::: "memory");
    }
}

// ---------------------------------------------------------------------------
// Finalize: y = accum/denom + b_gat; out = [mu | tanh(logvar)]
// ---------------------------------------------------------------------------
__global__ void __launch_bounds__(256) final_kernel(const float* __restrict__ b_gat,
                                                    float* __restrict__ out) {
    int idx = blockIdx.x * 256 + threadIdx.x;        // float4 index
    const int total = N_NODES * (F_OUT / 4);
    if (idx >= total) return;
    int node = idx >> 5;
    int q = idx & 31;
    int col = q * 4;

    float4 a = g_accum4[idx];
    float den = g_denom[node];
    float inv = (den > 0.f) ? (1.0f / den) : 0.f;
    float4 bg = *reinterpret_cast<const float4*>(&b_gat[col]);
    float4 y = make_float4(a.x * inv + bg.x, a.y * inv + bg.y,
                           a.z * inv + bg.z, a.w * inv + bg.w);

    if (col < 64) {
        *reinterpret_cast<float4*>(&out[(size_t)node * 64 + col]) = y;
    } else {
        float4 z = make_float4(tanhf(y.x), tanhf(y.y), tanhf(y.z), tanhf(y.w));
        *reinterpret_cast<float4*>(&out[(size_t)N_NODES * 64 + (size_t)node * 64 + (col - 64)]) = z;
    }
}

// ---------------------------------------------------------------------------
// Launch
// ---------------------------------------------------------------------------
extern "C" void kernel_launch(void* const* d_in, const int* in_sizes, int n_in,
                              void* d_out, int out_size) {
    const float* embed  = (const float*)d_in[0];
    const int*   src    = (const int*)d_in[1];
    const int*   dst    = (const int*)d_in[2];
    const float* W_lin  = (const float*)d_in[3];
    const float* b_lin  = (const float*)d_in[4];
    const float* W_gat  = (const float*)d_in[5];
    const float* attn_l = (const float*)d_in[6];
    const float* attn_r = (const float*)d_in[7];
    const float* b_gat  = (const float*)d_in[8];
    float* out = (float*)d_out;

    int num_edges = in_sizes[1];   // E

    init_kernel<<<2048, 256>>>();
    node_kernel<<<(N_NODES + 63) / 64, 256>>>(embed, W_lin, b_lin, W_gat, attn_l, attn_r);
    int edges_per_block = 8 * EPB;
    edge_kernel<<<(num_edges + edges_per_block - 1) / edges_per_block, 256>>>(src, dst, num_edges);
    final_kernel<<<(N_NODES * (F_OUT / 4) + 255) / 256, 256>>>(b_gat, out);
}

// round 3
// speedup vs baseline: 1.6320x; 1.2666x over previous
#include <cuda_runtime.h>
#include <math.h>
#include <stdint.h>

#define N_NODES 100000
#define E_EDGES 1600000
#define K_IN    192
#define F_LAT   64
#define F_OUT   128
#define NB_SCAN ((N_NODES + 1023) / 1024)   // 98

// ---------------------------------------------------------------------------
// Scratch (device globals)
// ---------------------------------------------------------------------------
__device__ float4 g_feat4[N_NODES * (F_OUT / 4)];   // feat [N,128]
__device__ float  g_el[N_NODES];
__device__ float  g_er[N_NODES];
__device__ int    g_cnt[N_NODES];                   // in-degree
__device__ int    g_start[N_NODES];                 // CSR offsets (exclusive scan)
__device__ int    g_cursor[N_NODES];                // scatter cursors
__device__ int    g_bsum[NB_SCAN];                  // per-block scan sums
__device__ int    g_boff[NB_SCAN];                  // scanned block offsets
__device__ int    g_srcS[E_EDGES];                  // dst-sorted src ids
__device__ float  g_eeS[E_EDGES];                   // dst-sorted exp(logit)

// ---------------------------------------------------------------------------
// Zero the degree histogram
// ---------------------------------------------------------------------------
__global__ void __launch_bounds__(256) zero_cnt() {
    int i = blockIdx.x * 256 + threadIdx.x;
    if (i < N_NODES) g_cnt[i] = 0;
}

// ---------------------------------------------------------------------------
// Fused node kernel: x = relu(embed@W1+b); feat = x@W2; el/er dots.
// 64-node tile, 256 threads, 4x4 microtile; embed smem tile reused as x.
// ---------------------------------------------------------------------------
__global__ void __launch_bounds__(256) node_kernel(const float* __restrict__ embed,
                                                   const float* __restrict__ Wl,
                                                   const float* __restrict__ bl,
                                                   const float* __restrict__ Wg,
                                                   const float* __restrict__ attn_l,
                                                   const float* __restrict__ attn_r) {
    __shared__ float sA[64][68];
    __shared__ float sW[64][64];
    __shared__ float sEl[64];
    __shared__ float sEr[64];

    int t = threadIdx.x;
    int base = blockIdx.x * 64;
    int tm = t >> 4;
    int tn = t & 15;

    if (t < 64) { sEl[t] = 0.f; sEr[t] = 0.f; }

    float acc[4][4];
#pragma unroll
    for (int r = 0; r < 4; r++)
#pragma unroll
        for (int c = 0; c < 4; c++) acc[r][c] = 0.f;

    // ---- phase A: x = relu(embed @ W_lin + b) ----
    for (int kc = 0; kc < 3; kc++) {
#pragma unroll
        for (int l = 0; l < 4; l++) {
            int idx = l * 256 + t;
            int r = idx >> 4;
            int c = (idx & 15) * 4;
            int node = base + r;
            float4 v = make_float4(0.f, 0.f, 0.f, 0.f);
            if (node < N_NODES)
                v = *reinterpret_cast<const float4*>(&embed[(size_t)node * K_IN + kc * 64 + c]);
            *reinterpret_cast<float4*>(&sA[r][c]) = v;
            float4 w = *reinterpret_cast<const float4*>(&Wl[(size_t)kc * 4096 + idx * 4]);
            *reinterpret_cast<float4*>(&sW[0][0] + idx * 4) = w;
        }
        __syncthreads();

#pragma unroll 16
        for (int k = 0; k < 64; k++) {
            float a0 = sA[tm * 4 + 0][k];
            float a1 = sA[tm * 4 + 1][k];
            float a2 = sA[tm * 4 + 2][k];
            float a3 = sA[tm * 4 + 3][k];
            float4 bb = *reinterpret_cast<const float4*>(&sW[k][tn * 4]);
            acc[0][0] += a0 * bb.x; acc[0][1] += a0 * bb.y; acc[0][2] += a0 * bb.z; acc[0][3] += a0 * bb.w;
            acc[1][0] += a1 * bb.x; acc[1][1] += a1 * bb.y; acc[1][2] += a1 * bb.z; acc[1][3] += a1 * bb.w;
            acc[2][0] += a2 * bb.x; acc[2][1] += a2 * bb.y; acc[2][2] += a2 * bb.z; acc[2][3] += a2 * bb.w;
            acc[3][0] += a3 * bb.x; acc[3][1] += a3 * bb.y; acc[3][2] += a3 * bb.z; acc[3][3] += a3 * bb.w;
        }
        __syncthreads();
    }

    {
        float4 bias = *reinterpret_cast<const float4*>(&bl[tn * 4]);
#pragma unroll
        for (int r = 0; r < 4; r++) {
            sA[tm * 4 + r][tn * 4 + 0] = fmaxf(acc[r][0] + bias.x, 0.f);
            sA[tm * 4 + r][tn * 4 + 1] = fmaxf(acc[r][1] + bias.y, 0.f);
            sA[tm * 4 + r][tn * 4 + 2] = fmaxf(acc[r][2] + bias.z, 0.f);
            sA[tm * 4 + r][tn * 4 + 3] = fmaxf(acc[r][3] + bias.w, 0.f);
        }
    }
    __syncthreads();

    // ---- phase B: feat = x @ W_gat (two 64-wide halves), el/er dots ----
    for (int nh = 0; nh < 2; nh++) {
#pragma unroll
        for (int l = 0; l < 4; l++) {
            int idx = l * 256 + t;
            int r = idx >> 4;
            int c = (idx & 15) * 4;
            float4 w = *reinterpret_cast<const float4*>(&Wg[(size_t)r * F_OUT + nh * 64 + c]);
            *reinterpret_cast<float4*>(&sW[0][0] + r * 64 + c) = w;
        }
        __syncthreads();

#pragma unroll
        for (int r = 0; r < 4; r++)
#pragma unroll
            for (int c = 0; c < 4; c++) acc[r][c] = 0.f;

#pragma unroll 16
        for (int k = 0; k < 64; k++) {
            float a0 = sA[tm * 4 + 0][k];
            float a1 = sA[tm * 4 + 1][k];
            float a2 = sA[tm * 4 + 2][k];
            float a3 = sA[tm * 4 + 3][k];
            float4 bb = *reinterpret_cast<const float4*>(&sW[k][tn * 4]);
            acc[0][0] += a0 * bb.x; acc[0][1] += a0 * bb.y; acc[0][2] += a0 * bb.z; acc[0][3] += a0 * bb.w;
            acc[1][0] += a1 * bb.x; acc[1][1] += a1 * bb.y; acc[1][2] += a1 * bb.z; acc[1][3] += a1 * bb.w;
            acc[2][0] += a2 * bb.x; acc[2][1] += a2 * bb.y; acc[2][2] += a2 * bb.z; acc[2][3] += a2 * bb.w;
            acc[3][0] += a3 * bb.x; acc[3][1] += a3 * bb.y; acc[3][2] += a3 * bb.z; acc[3][3] += a3 * bb.w;
        }

        float4 al = *reinterpret_cast<const float4*>(&attn_l[nh * 64 + tn * 4]);
        float4 ar = *reinterpret_cast<const float4*>(&attn_r[nh * 64 + tn * 4]);
#pragma unroll
        for (int r = 0; r < 4; r++) {
            int node = base + tm * 4 + r;
            if (node < N_NODES) {
                float4 o = make_float4(acc[r][0], acc[r][1], acc[r][2], acc[r][3]);
                g_feat4[(size_t)node * (F_OUT / 4) + (nh * 16 + tn)] = o;
                float pl = o.x * al.x + o.y * al.y + o.z * al.z + o.w * al.w;
                float pr = o.x * ar.x + o.y * ar.y + o.z * ar.z + o.w * ar.w;
                atomicAdd(&sEl[tm * 4 + r], pl);
                atomicAdd(&sEr[tm * 4 + r], pr);
            }
        }
        __syncthreads();
    }

    if (t < 64) {
        int node = base + t;
        if (node < N_NODES) {
            g_el[node] = sEl[t];
            g_er[node] = sEr[t];
        }
    }
}

// ---------------------------------------------------------------------------
// CSR build step 1: in-degree histogram of dst
// ---------------------------------------------------------------------------
__global__ void __launch_bounds__(256) hist_kernel(const int* __restrict__ dst,
                                                   int num_edges) {
    int i = blockIdx.x * 256 + threadIdx.x;
    int stride = gridDim.x * 256;
    for (int e = i; e < num_edges; e += stride)
        atomicAdd(&g_cnt[dst[e]], 1);
}

// ---------------------------------------------------------------------------
// CSR build step 2: exclusive scan (3 small kernels)
// ---------------------------------------------------------------------------
__global__ void __launch_bounds__(1024) scan_blocks() {
    __shared__ int sw[32];
    int tid = threadIdx.x;
    int lane = tid & 31;
    int wid = tid >> 5;
    int i = blockIdx.x * 1024 + tid;
    int v = (i < N_NODES) ? g_cnt[i] : 0;

    int x = v;
#pragma unroll
    for (int d = 1; d < 32; d <<= 1) {
        int y = __shfl_up_sync(0xffffffffu, x, d);
        if (lane >= d) x += y;
    }
    if (lane == 31) sw[wid] = x;
    __syncthreads();
    if (wid == 0) {
        int s = sw[lane];
#pragma unroll
        for (int d = 1; d < 32; d <<= 1) {
            int y = __shfl_up_sync(0xffffffffu, s, d);
            if (lane >= d) s += y;
        }
        sw[lane] = s;
    }
    __syncthreads();
    int incl = x + (wid > 0 ? sw[wid - 1] : 0);
    if (i < N_NODES) g_start[i] = incl - v;        // exclusive within block
    if (tid == 1023) g_bsum[blockIdx.x] = incl;
}

__global__ void scan_tops() {
    // single thread: 98 elements, trivial
    if (threadIdx.x == 0 && blockIdx.x == 0) {
        int run = 0;
        for (int b = 0; b < NB_SCAN; b++) {
            g_boff[b] = run;
            run += g_bsum[b];
        }
    }
}

__global__ void __launch_bounds__(256) scan_apply() {
    int i = blockIdx.x * 256 + threadIdx.x;
    if (i < N_NODES) {
        int s = g_start[i] + g_boff[i >> 10];
        g_start[i] = s;
        g_cursor[i] = s;
    }
}

// ---------------------------------------------------------------------------
// CSR build step 3: compute ee per edge, scatter (src, ee) into dst order
// ---------------------------------------------------------------------------
__global__ void __launch_bounds__(256) scatter_kernel(const int* __restrict__ src,
                                                      const int* __restrict__ dst,
                                                      int num_edges) {
    int i = blockIdx.x * 256 + threadIdx.x;
    int stride = gridDim.x * 256;
    for (int e = i; e < num_edges; e += stride) {
        int s = src[e];
        int d = dst[e];
        float logit = g_el[s] + g_er[d];
        logit = (logit > 0.f) ? logit : 0.2f * logit;
        float ee = __expf(logit);
        int pos = atomicAdd(&g_cursor[d], 1);
        g_srcS[pos] = s;
        g_eeS[pos] = ee;
    }
}

// ---------------------------------------------------------------------------
// Aggregation: one warp per dst node. Gather feat rows of its segment,
// accumulate numerator + denominator in registers, write y directly to out.
//   y = acc/denom + b_gat;  out = [mu (N x 64) | tanh(logvar) (N x 64)]
// Lane l owns float4 columns [4l, 4l+4).
// ---------------------------------------------------------------------------
__global__ void __launch_bounds__(256) agg_kernel(const float* __restrict__ b_gat,
                                                  float* __restrict__ out) {
    int warp = (blockIdx.x * 256 + threadIdx.x) >> 5;
    int lane = threadIdx.x & 31;
    if (warp >= N_NODES) return;

    int beg = g_start[warp];
    int deg = g_cnt[warp];
    int end = beg + deg;

    float4 acc = make_float4(0.f, 0.f, 0.f, 0.f);
    float dsum = 0.f;

    int j = beg;
    for (; j + 4 <= end; j += 4) {
        int s0 = g_srcS[j + 0], s1 = g_srcS[j + 1], s2 = g_srcS[j + 2], s3 = g_srcS[j + 3];
        float e0 = g_eeS[j + 0], e1 = g_eeS[j + 1], e2 = g_eeS[j + 2], e3 = g_eeS[j + 3];
        float4 f0 = g_feat4[(size_t)s0 * 32 + lane];
        float4 f1 = g_feat4[(size_t)s1 * 32 + lane];
        float4 f2 = g_feat4[(size_t)s2 * 32 + lane];
        float4 f3 = g_feat4[(size_t)s3 * 32 + lane];
        acc.x += e0 * f0.x + e1 * f1.x + e2 * f2.x + e3 * f3.x;
        acc.y += e0 * f0.y + e1 * f1.y + e2 * f2.y + e3 * f3.y;
        acc.z += e0 * f0.z + e1 * f1.z + e2 * f2.z + e3 * f3.z;
        acc.w += e0 * f0.w + e1 * f1.w + e2 * f2.w + e3 * f3.w;
        dsum += (e0 + e1) + (e2 + e3);
    }
    for (; j < end; j++) {
        int s = g_srcS[j];
        float ee = g_eeS[j];
        float4 f = g_feat4[(size_t)s * 32 + lane];
        acc.x += ee * f.x; acc.y += ee * f.y; acc.z += ee * f.z; acc.w += ee * f.w;
        dsum += ee;
    }

    float inv = (dsum > 0.f) ? (1.0f / dsum) : 0.f;
    float4 bg = *reinterpret_cast<const float4*>(&b_gat[lane * 4]);
    float4 y = make_float4(acc.x * inv + bg.x, acc.y * inv + bg.y,
                           acc.z * inv + bg.z, acc.w * inv + bg.w);

    if (lane < 16) {
        *reinterpret_cast<float4*>(&out[(size_t)warp * 64 + lane * 4]) = y;
    } else {
        float4 z = make_float4(tanhf(y.x), tanhf(y.y), tanhf(y.z), tanhf(y.w));
        *reinterpret_cast<float4*>(&out[(size_t)N_NODES * 64 + (size_t)warp * 64 + (lane - 16) * 4]) = z;
    }
}

// ---------------------------------------------------------------------------
// Launch
// ---------------------------------------------------------------------------
extern "C" void kernel_launch(void* const* d_in, const int* in_sizes, int n_in,
                              void* d_out, int out_size) {
    const float* embed  = (const float*)d_in[0];
    const int*   src    = (const int*)d_in[1];
    const int*   dst    = (const int*)d_in[2];
    const float* W_lin  = (const float*)d_in[3];
    const float* b_lin  = (const float*)d_in[4];
    const float* W_gat  = (const float*)d_in[5];
    const float* attn_l = (const float*)d_in[6];
    const float* attn_r = (const float*)d_in[7];
    const float* b_gat  = (const float*)d_in[8];
    float* out = (float*)d_out;

    int num_edges = in_sizes[1];   // E

    zero_cnt<<<(N_NODES + 255) / 256, 256>>>();
    node_kernel<<<(N_NODES + 63) / 64, 256>>>(embed, W_lin, b_lin, W_gat, attn_l, attn_r);
    hist_kernel<<<1184, 256>>>(dst, num_edges);
    scan_blocks<<<NB_SCAN, 1024>>>();
    scan_tops<<<1, 32>>>();
    scan_apply<<<(N_NODES + 255) / 256, 256>>>();
    scatter_kernel<<<1184, 256>>>(src, dst, num_edges);
    agg_kernel<<<(N_NODES * 32 + 255) / 256, 256>>>(b_gat, out);
}